// round 15
// baseline (speedup 1.0000x reference)
#include <cuda_runtime.h>

typedef unsigned long long u64;

#define THREADS 512
#define WARPS 16
#define PAIRS 6            // 6 row-pairs (12 rows) per warp
#define HSTRIDE 100        // u64 slots per pair (even => 16B-aligned k-pairs)
#define ROWS_PER_BLOCK 192
#define GSTRIDE 509        // floats per group in pass chunk; odd => conflict-free

// smem layout (float offsets).
// R0: W1 (0..6400) + W4 (6400..16400); overlaid by chunk B after layer 2.
// R2: 16288 floats; first 6400 hold pass-A weights [k][64] until pass A is
//     done, then chunk C is cp.async'd over it during pass B.
#define OFF_R0 0
#define OFF_B1 16400
#define OFF_B4 16500
#define OFF_B2 16600
#define OFF_R2 16984
#define N_CHUNK 16288                       // 32*GSTRIDE
#define OFF_H  (OFF_R2 + N_CHUNK)           // 33272; *4 % 16 == 0
#define N_H_U64 (WARPS * PAIRS * HSTRIDE)   // 9600 u64 = 19200 floats
#define SMEM_BYTES ((OFF_H + 2 * N_H_U64) * 4)   // 209888

// ---------- packed f32x2 helpers (sm_103a) ----------
__device__ __forceinline__ u64 pack2(float lo, float hi) {
    u64 r; asm("mov.b64 %0, {%1,%2};" : "=l"(r) : "f"(lo), "f"(hi)); return r;
}
__device__ __forceinline__ u64 splat2(float v) { return pack2(v, v); }
__device__ __forceinline__ void unpack2(u64 p, float& lo, float& hi) {
    asm("mov.b64 {%0,%1}, %2;" : "=f"(lo), "=f"(hi) : "l"(p));
}
__device__ __forceinline__ u64 fma2(u64 a, u64 b, u64 c) {
    u64 d; asm("fma.rn.f32x2 %0, %1, %2, %3;" : "=l"(d) : "l"(a), "l"(b), "l"(c));
    return d;
}

// cp.async 4B scattered copy (global -> shared) for the transposed restages.
__device__ __forceinline__ void cp_async4(void* dst_smem, const void* src) {
    unsigned d = (unsigned)__cvta_generic_to_shared(dst_smem);
    asm volatile("cp.async.ca.shared.global [%0], [%1], 4;" :: "r"(d), "l"(src));
}

__device__ __forceinline__ void prefetch_l2(const void* p) {
    asm volatile("prefetch.global.L2 [%0];" :: "l"(p));
}

// Accurate tanh via MUFU.EX2 (__expf, rel ~2^-22); tanh.approx would flip argmaxes.
__device__ __forceinline__ float tanh_acc(float x) {
    x = fminf(fmaxf(x, -15.f), 15.f);
    float e = __expf(2.f * x);
    return (e - 1.f) / (e + 1.f);
}

// Dense layer (K -> 100) + tanh on this warp's 12 rows (6 f32x2 row-pairs).
template <int K>
__device__ __forceinline__ void dense_tanh_layer(
    const float* __restrict__ sW, const float* __restrict__ sB,
    u64* hsw, int lane)
{
    u64 acc[PAIRS][4];
    if (lane < 25) {
        #pragma unroll
        for (int j = 0; j < 4; j++) {
            u64 b = splat2(sB[4 * lane + j]);
            #pragma unroll
            for (int p = 0; p < PAIRS; p++) acc[p][j] = b;
        }
        #pragma unroll 4
        for (int k = 0; k < K; k += 2) {
            float4 wa = *(const float4*)&sW[k * 100 + 4 * lane];
            float4 wb = *(const float4*)&sW[(k + 1) * 100 + 4 * lane];
            u64 a0 = splat2(wa.x), a1 = splat2(wa.y), a2 = splat2(wa.z), a3 = splat2(wa.w);
            u64 c0 = splat2(wb.x), c1 = splat2(wb.y), c2 = splat2(wb.z), c3 = splat2(wb.w);
            #pragma unroll
            for (int p = 0; p < PAIRS; p++) {
                ulonglong2 h = *(const ulonglong2*)&hsw[p * HSTRIDE + k];
                acc[p][0] = fma2(h.x, a0, acc[p][0]);
                acc[p][1] = fma2(h.x, a1, acc[p][1]);
                acc[p][2] = fma2(h.x, a2, acc[p][2]);
                acc[p][3] = fma2(h.x, a3, acc[p][3]);
                acc[p][0] = fma2(h.y, c0, acc[p][0]);
                acc[p][1] = fma2(h.y, c1, acc[p][1]);
                acc[p][2] = fma2(h.y, c2, acc[p][2]);
                acc[p][3] = fma2(h.y, c3, acc[p][3]);
            }
        }
    }
    __syncwarp();
    if (lane < 25) {
        #pragma unroll
        for (int p = 0; p < PAIRS; p++) {
            #pragma unroll
            for (int j = 0; j < 4; j++) {
                float lo, hi; unpack2(acc[p][j], lo, hi);
                hsw[p * HSTRIDE + 4 * lane + j] = pack2(tanh_acc(lo), tanh_acc(hi));
            }
        }
    }
    __syncwarp();
}

// L2-prefetch this warp's gumbel rows for one pass (cols colOff..colOff+159).
// 640 bytes per row = 5 x 128B lines.
__device__ __forceinline__ void prefetch_gumbel(
    const float* __restrict__ gumbel, int rowBase, int lane, int colOff, int nrows)
{
    for (int i = lane; i < 2 * PAIRS * 5; i += 32) {
        int r = rowBase + i / 5;
        if (r < nrows)
            prefetch_l2(gumbel + (size_t)r * 320 + colOff + (i % 5) * 32);
    }
}

// One gumbel pass over 32 groups; lane owns global group G = gbase + lane
// (output cols 64+5G..64+5G+4). Chunk layout: sChunk[lane*GSTRIDE + 5*k + j].
__device__ __forceinline__ void pass_groups(
    const float* __restrict__ sChunk, const float* __restrict__ sB2,
    const u64* hsw, float* __restrict__ out,
    const float* __restrict__ gumbel,
    int rowBase, int lane, int gbase, int nrows)
{
    const int G = gbase + lane;
    u64 acc[PAIRS][5];
    #pragma unroll
    for (int j = 0; j < 5; j++) {
        u64 b = splat2(sB2[64 + 5 * G + j]);
        #pragma unroll
        for (int p = 0; p < PAIRS; p++) acc[p][j] = b;
    }
    const float* wbase = &sChunk[lane * GSTRIDE];
    #pragma unroll 2
    for (int k = 0; k < 100; k += 2) {
        const float* w = wbase + 5 * k;
        u64 s0 = splat2(w[0]), s1 = splat2(w[1]), s2 = splat2(w[2]),
            s3 = splat2(w[3]), s4 = splat2(w[4]);
        u64 t0 = splat2(w[5]), t1 = splat2(w[6]), t2 = splat2(w[7]),
            t3 = splat2(w[8]), t4 = splat2(w[9]);
        #pragma unroll
        for (int p = 0; p < PAIRS; p++) {
            ulonglong2 h = *(const ulonglong2*)&hsw[p * HSTRIDE + k];
            acc[p][0] = fma2(h.x, s0, acc[p][0]);
            acc[p][1] = fma2(h.x, s1, acc[p][1]);
            acc[p][2] = fma2(h.x, s2, acc[p][2]);
            acc[p][3] = fma2(h.x, s3, acc[p][3]);
            acc[p][4] = fma2(h.x, s4, acc[p][4]);
            acc[p][0] = fma2(h.y, t0, acc[p][0]);
            acc[p][1] = fma2(h.y, t1, acc[p][1]);
            acc[p][2] = fma2(h.y, t2, acc[p][2]);
            acc[p][3] = fma2(h.y, t3, acc[p][3]);
            acc[p][4] = fma2(h.y, t4, acc[p][4]);
        }
    }
    // Straight-through gumbel-softmax == one-hot(argmax(logit + gumbel)).
    // (gumbel added after the k-loop to keep FP ordering == reference;
    //  gumbel rows were L2-prefetched one phase ago.)
    #pragma unroll
    for (int p = 0; p < PAIRS; p++) {
        float v0[5], v1[5];
        #pragma unroll
        for (int j = 0; j < 5; j++) unpack2(acc[p][j], v0[j], v1[j]);
        int r0 = rowBase + 2 * p;
        #pragma unroll
        for (int half = 0; half < 2; half++) {
            int r = r0 + half;
            if (r >= nrows) continue;
            const float* v = half ? v1 : v0;
            const float* g = gumbel + (size_t)r * 320 + 5 * G;
            int am = 0;
            float best = v[0] + g[0];
            #pragma unroll
            for (int j = 1; j < 5; j++) {
                float t = v[j] + g[j];
                if (t > best) { best = t; am = j; }
            }
            float* o = out + (size_t)r * 384 + 64 + 5 * G;
            #pragma unroll
            for (int j = 0; j < 5; j++) o[j] = (j == am) ? 1.f : 0.f;
        }
    }
}

__global__ void __launch_bounds__(THREADS, 1)
mlp_fused_kernel(const float* __restrict__ x,
                 const float* __restrict__ W1, const float* __restrict__ b1,
                 const float* __restrict__ W4, const float* __restrict__ b4,
                 const float* __restrict__ W2, const float* __restrict__ b2,
                 const float* __restrict__ gumbel,
                 float* __restrict__ out, int nrows)
{
    extern __shared__ float smem[];
    float* sW1 = smem + OFF_R0;
    float* sW4 = smem + OFF_R0 + 6400;
    float* sB1 = smem + OFF_B1;
    float* sB4 = smem + OFF_B4;
    float* sB2 = smem + OFF_B2;
    float* sR2 = smem + OFF_R2;          // pass-A weights, then chunk C
    float* sBufB = smem + OFF_R0;        // chunk B overlays W1/W4 after layer 2
    u64*   sH  = (u64*)(smem + OFF_H);

    const int tid = threadIdx.x;
    const int lane = tid & 31;
    const int wid = tid >> 5;
    const int rowBase = blockIdx.x * ROWS_PER_BLOCK + wid * (2 * PAIRS);
    u64* hsw = sH + wid * PAIRS * HSTRIDE;

    // ---- stage W1, W4, biases, pass-A weights (W2 cols 0..63 as [k][64]) ----
    {
        const float4* s1 = (const float4*)W1; float4* d1 = (float4*)sW1;
        for (int i = tid; i < 1600; i += THREADS) d1[i] = s1[i];
        const float4* s4 = (const float4*)W4; float4* d4 = (float4*)sW4;
        for (int i = tid; i < 2500; i += THREADS) d4[i] = s4[i];
        for (int i = tid; i < 100; i += THREADS) { sB1[i] = b1[i]; sB4[i] = b4[i]; }
        for (int i = tid; i < 384; i += THREADS) sB2[i] = b2[i];
        float4* dc = (float4*)sR2;   // pass-A weights at front of R2
        for (int i = tid; i < 100 * 16; i += THREADS) {
            int k = i >> 4, c4 = i & 15;
            dc[i] = *(const float4*)(W2 + k * 384 + 4 * c4);
        }
    }
    // ---- stage x for this warp's 12 rows, as row-pairs ----
    {
        float* hswF = (float*)hsw;
        for (int idx = lane; idx < 2 * PAIRS * 64; idx += 32) {
            int r = idx >> 6, k = idx & 63;
            int gr = rowBase + r;
            float xv = (gr < nrows) ? x[(size_t)gr * 64 + k] : 0.f;
            hswF[((r >> 1) * HSTRIDE + k) * 2 + (r & 1)] = xv;
        }
    }
    __syncthreads();

    // ---- layers 1 and 2 (warp-private) ----
    dense_tanh_layer<64>(sW1, sB1, hsw, lane);
    dense_tanh_layer<100>(sW4, sB4, hsw, lane);
    __syncthreads();   // all warps done with W1/W4 before chunk B overwrites them

    // ---- prefetch chunk B into dead W1/W4 region (lands under pass A) ----
    for (int i = tid; i < 16000; i += THREADS) {
        int k = i / 160, c = i - k * 160;
        cp_async4(&sBufB[(c / 5) * GSTRIDE + 5 * k + (c % 5)],
                  W2 + k * 384 + 64 + c);
    }
    asm volatile("cp.async.commit_group;");   // group: {B}

    // ---- L2-prefetch pass-B gumbel rows (consumed at end of pass B) ----
    prefetch_gumbel(gumbel, rowBase, lane, 0, nrows);

    // ---- pass A: softmax columns 0..63 (2 cols/lane), weights in R2 front ----
    {
        u64 acc[PAIRS][2];
        u64 bA = splat2(sB2[2 * lane]), bB = splat2(sB2[2 * lane + 1]);
        #pragma unroll
        for (int p = 0; p < PAIRS; p++) { acc[p][0] = bA; acc[p][1] = bB; }
        #pragma unroll 4
        for (int k = 0; k < 100; k += 2) {
            float2 wa = *(const float2*)&sR2[k * 64 + 2 * lane];
            float2 wb = *(const float2*)&sR2[(k + 1) * 64 + 2 * lane];
            u64 a0 = splat2(wa.x), a1 = splat2(wa.y);
            u64 c0 = splat2(wb.x), c1 = splat2(wb.y);
            #pragma unroll
            for (int p = 0; p < PAIRS; p++) {
                ulonglong2 h = *(const ulonglong2*)&hsw[p * HSTRIDE + k];
                acc[p][0] = fma2(h.x, a0, acc[p][0]);
                acc[p][1] = fma2(h.x, a1, acc[p][1]);
                acc[p][0] = fma2(h.y, c0, acc[p][0]);
                acc[p][1] = fma2(h.y, c1, acc[p][1]);
            }
        }
        #pragma unroll
        for (int p = 0; p < PAIRS; p++) {
            float a0, a1, c0, c1;
            unpack2(acc[p][0], a0, a1);
            unpack2(acc[p][1], c0, c1);
            #pragma unroll
            for (int half = 0; half < 2; half++) {
                float va = half ? a1 : a0;
                float vb = half ? c1 : c0;
                float m = fmaxf(va, vb);
                #pragma unroll
                for (int off = 16; off > 0; off >>= 1)
                    m = fmaxf(m, __shfl_xor_sync(0xffffffffu, m, off));
                float e0 = __expf(va - m), e1 = __expf(vb - m);
                float s = e0 + e1;
                #pragma unroll
                for (int off = 16; off > 0; off >>= 1)
                    s += __shfl_xor_sync(0xffffffffu, s, off);
                float inv = 1.0f / s;
                int r = rowBase + 2 * p + half;
                if (r < nrows) {
                    float2 o; o.x = e0 * inv; o.y = e1 * inv;
                    *(float2*)&out[(size_t)r * 384 + 2 * lane] = o;
                }
            }
        }
    }

    // ---- all warps done reading pass-A weights; prefetch chunk C over them
    //      (lands under pass B) ----
    __syncthreads();
    for (int i = tid; i < 16000; i += THREADS) {
        int k = i / 160, c = i - k * 160;
        cp_async4(&sR2[(c / 5) * GSTRIDE + 5 * k + (c % 5)],
                  W2 + k * 384 + 224 + c);
    }
    asm volatile("cp.async.commit_group;");              // groups: {B, C}
    asm volatile("cp.async.wait_group 1;" ::: "memory"); // B complete
    __syncthreads();

    // ---- L2-prefetch pass-C gumbel rows, then pass B ----
    prefetch_gumbel(gumbel, rowBase, lane, 160, nrows);
    pass_groups(sBufB, sB2, hsw, out, gumbel, rowBase, lane, 0, nrows);

    // ---- pass C: chunk already resident in R2 ----
    asm volatile("cp.async.wait_group 0;" ::: "memory"); // C complete
    __syncthreads();
    pass_groups(sR2, sB2, hsw, out, gumbel, rowBase, lane, 32, nrows);
}

extern "C" void kernel_launch(void* const* d_in, const int* in_sizes, int n_in,
                              void* d_out, int out_size)
{
    const float* x      = (const float*)d_in[0];
    const float* W1     = (const float*)d_in[1];
    const float* b1     = (const float*)d_in[2];
    const float* W4     = (const float*)d_in[3];
    const float* b4     = (const float*)d_in[4];
    const float* W2     = (const float*)d_in[5];
    const float* b2     = (const float*)d_in[6];
    const float* gumbel = (const float*)d_in[7];
    float* out = (float*)d_out;

    int nrows = in_sizes[0] / 64;
    int blocks = (nrows + ROWS_PER_BLOCK - 1) / ROWS_PER_BLOCK;

    cudaFuncSetAttribute(mlp_fused_kernel,
                         cudaFuncAttributeMaxDynamicSharedMemorySize, SMEM_BYTES);
    mlp_fused_kernel<<<blocks, THREADS, SMEM_BYTES>>>(
        x, W1, b1, W4, b4, W2, b2, gumbel, out, nrows);
}

// round 17
// speedup vs baseline: 1.5967x; 1.5967x over previous
#include <cuda_runtime.h>

typedef unsigned long long u64;

#define THREADS 512
#define WARPS 16
#define PAIRS 6            // 6 row-pairs (12 rows) per warp
#define HSTRIDE 100        // u64 slots per pair (even => 16B-aligned k-pairs)
#define ROWS_PER_BLOCK 192
#define GSTRIDE 509        // floats per group in pass chunk; odd => conflict-free

// smem layout (float offsets). W1/W4 region is reused as the pass-B/C weight
// chunk after layer 2 (both dead by then; 16288 <= 16400).
#define OFF_W1 0
#define OFF_W4 6400
#define OFF_CHUNK 0
#define OFF_B1 16400
#define OFF_B4 16500
#define OFF_B2 16600
#define OFF_WA 16984                        // pass-A weights [k][64], 6400 floats
#define OFF_H  23384                        // *4 = 93536, 16B aligned
#define N_H_U64 (WARPS * PAIRS * HSTRIDE)   // 9600 u64 = 19200 floats
#define SMEM_BYTES ((OFF_H + 2 * N_H_U64) * 4)   // 170336

// ---------- packed f32x2 helpers (sm_103a) ----------
__device__ __forceinline__ u64 pack2(float lo, float hi) {
    u64 r; asm("mov.b64 %0, {%1,%2};" : "=l"(r) : "f"(lo), "f"(hi)); return r;
}
__device__ __forceinline__ u64 splat2(float v) { return pack2(v, v); }
__device__ __forceinline__ void unpack2(u64 p, float& lo, float& hi) {
    asm("mov.b64 {%0,%1}, %2;" : "=f"(lo), "=f"(hi) : "l"(p));
}
__device__ __forceinline__ u64 fma2(u64 a, u64 b, u64 c) {
    u64 d; asm("fma.rn.f32x2 %0, %1, %2, %3;" : "=l"(d) : "l"(a), "l"(b), "l"(c));
    return d;
}

// cp.async 4B scattered copy (global -> shared) for the transposed restages.
__device__ __forceinline__ void cp_async4(void* dst_smem, const void* src) {
    unsigned d = (unsigned)__cvta_generic_to_shared(dst_smem);
    asm volatile("cp.async.ca.shared.global [%0], [%1], 4;" :: "r"(d), "l"(src));
}

__device__ __forceinline__ void prefetch_l2(const void* p) {
    asm volatile("prefetch.global.L2 [%0];" :: "l"(p));
}

// Accurate tanh via MUFU.EX2 (__expf, rel ~2^-22); tanh.approx would flip argmaxes.
__device__ __forceinline__ float tanh_acc(float x) {
    x = fminf(fmaxf(x, -15.f), 15.f);
    float e = __expf(2.f * x);
    return (e - 1.f) / (e + 1.f);
}

// Dense layer (K -> 100) + tanh on this warp's 12 rows (6 f32x2 row-pairs).
template <int K>
__device__ __forceinline__ void dense_tanh_layer(
    const float* __restrict__ sW, const float* __restrict__ sB,
    u64* hsw, int lane)
{
    u64 acc[PAIRS][4];
    if (lane < 25) {
        #pragma unroll
        for (int j = 0; j < 4; j++) {
            u64 b = splat2(sB[4 * lane + j]);
            #pragma unroll
            for (int p = 0; p < PAIRS; p++) acc[p][j] = b;
        }
        #pragma unroll 4
        for (int k = 0; k < K; k += 2) {
            float4 wa = *(const float4*)&sW[k * 100 + 4 * lane];
            float4 wb = *(const float4*)&sW[(k + 1) * 100 + 4 * lane];
            u64 a0 = splat2(wa.x), a1 = splat2(wa.y), a2 = splat2(wa.z), a3 = splat2(wa.w);
            u64 c0 = splat2(wb.x), c1 = splat2(wb.y), c2 = splat2(wb.z), c3 = splat2(wb.w);
            #pragma unroll
            for (int p = 0; p < PAIRS; p++) {
                ulonglong2 h = *(const ulonglong2*)&hsw[p * HSTRIDE + k];
                acc[p][0] = fma2(h.x, a0, acc[p][0]);
                acc[p][1] = fma2(h.x, a1, acc[p][1]);
                acc[p][2] = fma2(h.x, a2, acc[p][2]);
                acc[p][3] = fma2(h.x, a3, acc[p][3]);
                acc[p][0] = fma2(h.y, c0, acc[p][0]);
                acc[p][1] = fma2(h.y, c1, acc[p][1]);
                acc[p][2] = fma2(h.y, c2, acc[p][2]);
                acc[p][3] = fma2(h.y, c3, acc[p][3]);
            }
        }
    }
    __syncwarp();
    if (lane < 25) {
        #pragma unroll
        for (int p = 0; p < PAIRS; p++) {
            #pragma unroll
            for (int j = 0; j < 4; j++) {
                float lo, hi; unpack2(acc[p][j], lo, hi);
                hsw[p * HSTRIDE + 4 * lane + j] = pack2(tanh_acc(lo), tanh_acc(hi));
            }
        }
    }
    __syncwarp();
}

// L2-prefetch this warp's gumbel rows for one pass (cols colOff..colOff+159).
__device__ __forceinline__ void prefetch_gumbel(
    const float* __restrict__ gumbel, int rowBase, int lane, int colOff, int nrows)
{
    for (int i = lane; i < 2 * PAIRS * 5; i += 32) {
        int r = rowBase + i / 5;
        if (r < nrows)
            prefetch_l2(gumbel + (size_t)r * 320 + colOff + (i % 5) * 32);
    }
}

// One gumbel pass over 32 groups; lane owns global group G = gbase + lane
// (output cols 64+5G..64+5G+4). Chunk layout: sChunk[lane*GSTRIDE + 5*k + j].
__device__ __forceinline__ void pass_groups(
    const float* __restrict__ sChunk, const float* __restrict__ sB2,
    const u64* hsw, float* __restrict__ out,
    const float* __restrict__ gumbel,
    int rowBase, int lane, int gbase, int nrows)
{
    const int G = gbase + lane;
    u64 acc[PAIRS][5];
    #pragma unroll
    for (int j = 0; j < 5; j++) {
        u64 b = splat2(sB2[64 + 5 * G + j]);
        #pragma unroll
        for (int p = 0; p < PAIRS; p++) acc[p][j] = b;
    }
    const float* wbase = &sChunk[lane * GSTRIDE];
    #pragma unroll 2
    for (int k = 0; k < 100; k += 2) {
        const float* w = wbase + 5 * k;
        u64 s0 = splat2(w[0]), s1 = splat2(w[1]), s2 = splat2(w[2]),
            s3 = splat2(w[3]), s4 = splat2(w[4]);
        u64 t0 = splat2(w[5]), t1 = splat2(w[6]), t2 = splat2(w[7]),
            t3 = splat2(w[8]), t4 = splat2(w[9]);
        #pragma unroll
        for (int p = 0; p < PAIRS; p++) {
            ulonglong2 h = *(const ulonglong2*)&hsw[p * HSTRIDE + k];
            acc[p][0] = fma2(h.x, s0, acc[p][0]);
            acc[p][1] = fma2(h.x, s1, acc[p][1]);
            acc[p][2] = fma2(h.x, s2, acc[p][2]);
            acc[p][3] = fma2(h.x, s3, acc[p][3]);
            acc[p][4] = fma2(h.x, s4, acc[p][4]);
            acc[p][0] = fma2(h.y, t0, acc[p][0]);
            acc[p][1] = fma2(h.y, t1, acc[p][1]);
            acc[p][2] = fma2(h.y, t2, acc[p][2]);
            acc[p][3] = fma2(h.y, t3, acc[p][3]);
            acc[p][4] = fma2(h.y, t4, acc[p][4]);
        }
    }
    // Straight-through gumbel-softmax == one-hot(argmax(logit + gumbel)).
    // (gumbel added after the k-loop to keep FP ordering == reference;
    //  rows were L2-prefetched one phase ago.)
    #pragma unroll
    for (int p = 0; p < PAIRS; p++) {
        float v0[5], v1[5];
        #pragma unroll
        for (int j = 0; j < 5; j++) unpack2(acc[p][j], v0[j], v1[j]);
        int r0 = rowBase + 2 * p;
        #pragma unroll
        for (int half = 0; half < 2; half++) {
            int r = r0 + half;
            if (r >= nrows) continue;
            const float* v = half ? v1 : v0;
            const float* g = gumbel + (size_t)r * 320 + 5 * G;
            int am = 0;
            float best = v[0] + g[0];
            #pragma unroll
            for (int j = 1; j < 5; j++) {
                float t = v[j] + g[j];
                if (t > best) { best = t; am = j; }
            }
            float* o = out + (size_t)r * 384 + 64 + 5 * G;
            #pragma unroll
            for (int j = 0; j < 5; j++) o[j] = (j == am) ? 1.f : 0.f;
        }
    }
}

__global__ void __launch_bounds__(THREADS, 1)
mlp_fused_kernel(const float* __restrict__ x,
                 const float* __restrict__ W1, const float* __restrict__ b1,
                 const float* __restrict__ W4, const float* __restrict__ b4,
                 const float* __restrict__ W2, const float* __restrict__ b2,
                 const float* __restrict__ gumbel,
                 float* __restrict__ out, int nrows)
{
    extern __shared__ float smem[];
    float* sW1 = smem + OFF_W1;
    float* sW4 = smem + OFF_W4;
    float* sB1 = smem + OFF_B1;
    float* sB4 = smem + OFF_B4;
    float* sB2 = smem + OFF_B2;
    float* sWA = smem + OFF_WA;
    u64*   sH  = (u64*)(smem + OFF_H);
    float* sChunk = smem + OFF_CHUNK;   // overlays W1/W4 after layer 2

    const int tid = threadIdx.x;
    const int lane = tid & 31;
    const int wid = tid >> 5;
    const int rowBase = blockIdx.x * ROWS_PER_BLOCK + wid * (2 * PAIRS);
    u64* hsw = sH + wid * PAIRS * HSTRIDE;

    // ---- stage W1, W4, biases, pass-A weights (W2 cols 0..63 as [k][64]) ----
    {
        const float4* s1 = (const float4*)W1; float4* d1 = (float4*)sW1;
        for (int i = tid; i < 1600; i += THREADS) d1[i] = s1[i];
        const float4* s4 = (const float4*)W4; float4* d4 = (float4*)sW4;
        for (int i = tid; i < 2500; i += THREADS) d4[i] = s4[i];
        for (int i = tid; i < 100; i += THREADS) { sB1[i] = b1[i]; sB4[i] = b4[i]; }
        for (int i = tid; i < 384; i += THREADS) sB2[i] = b2[i];
        float4* dc = (float4*)sWA;
        for (int i = tid; i < 100 * 16; i += THREADS) {
            int k = i >> 4, c4 = i & 15;
            dc[i] = *(const float4*)(W2 + k * 384 + 4 * c4);
        }
    }
    // ---- stage x for this warp's 12 rows, as row-pairs ----
    {
        float* hswF = (float*)hsw;
        for (int idx = lane; idx < 2 * PAIRS * 64; idx += 32) {
            int r = idx >> 6, k = idx & 63;
            int gr = rowBase + r;
            float xv = (gr < nrows) ? x[(size_t)gr * 64 + k] : 0.f;
            hswF[((r >> 1) * HSTRIDE + k) * 2 + (r & 1)] = xv;
        }
    }
    __syncthreads();

    // ---- layers 1 and 2 (warp-private) ----
    dense_tanh_layer<64>(sW1, sB1, hsw, lane);
    dense_tanh_layer<100>(sW4, sB4, hsw, lane);
    __syncthreads();   // all warps done with W1/W4 before chunk B overwrites them

    // ---- prefetch pass-B chunk into the dead W1/W4 region; lands under pass A ----
    for (int i = tid; i < 16000; i += THREADS) {
        int k = i / 160, c = i - k * 160;
        cp_async4(&sChunk[(c / 5) * GSTRIDE + 5 * k + (c % 5)],
                  W2 + k * 384 + 64 + c);
    }
    asm volatile("cp.async.commit_group;");

    // ---- L2-prefetch pass-B gumbel rows (consumed at end of pass B) ----
    prefetch_gumbel(gumbel, rowBase, lane, 0, nrows);

    // ---- pass A: softmax columns 0..63 (2 cols/lane) ----
    {
        u64 acc[PAIRS][2];
        u64 bA = splat2(sB2[2 * lane]), bB = splat2(sB2[2 * lane + 1]);
        #pragma unroll
        for (int p = 0; p < PAIRS; p++) { acc[p][0] = bA; acc[p][1] = bB; }
        #pragma unroll 4
        for (int k = 0; k < 100; k += 2) {
            float2 wa = *(const float2*)&sWA[k * 64 + 2 * lane];
            float2 wb = *(const float2*)&sWA[(k + 1) * 64 + 2 * lane];
            u64 a0 = splat2(wa.x), a1 = splat2(wa.y);
            u64 c0 = splat2(wb.x), c1 = splat2(wb.y);
            #pragma unroll
            for (int p = 0; p < PAIRS; p++) {
                ulonglong2 h = *(const ulonglong2*)&hsw[p * HSTRIDE + k];
                acc[p][0] = fma2(h.x, a0, acc[p][0]);
                acc[p][1] = fma2(h.x, a1, acc[p][1]);
                acc[p][0] = fma2(h.y, c0, acc[p][0]);
                acc[p][1] = fma2(h.y, c1, acc[p][1]);
            }
        }
        #pragma unroll
        for (int p = 0; p < PAIRS; p++) {
            float a0, a1, c0, c1;
            unpack2(acc[p][0], a0, a1);
            unpack2(acc[p][1], c0, c1);
            #pragma unroll
            for (int half = 0; half < 2; half++) {
                float va = half ? a1 : a0;
                float vb = half ? c1 : c0;
                float m = fmaxf(va, vb);
                #pragma unroll
                for (int off = 16; off > 0; off >>= 1)
                    m = fmaxf(m, __shfl_xor_sync(0xffffffffu, m, off));
                float e0 = __expf(va - m), e1 = __expf(vb - m);
                float s = e0 + e1;
                #pragma unroll
                for (int off = 16; off > 0; off >>= 1)
                    s += __shfl_xor_sync(0xffffffffu, s, off);
                float inv = 1.0f / s;
                int r = rowBase + 2 * p + half;
                if (r < nrows) {
                    float2 o; o.x = e0 * inv; o.y = e1 * inv;
                    *(float2*)&out[(size_t)r * 384 + 2 * lane] = o;
                }
            }
        }
    }

    // ---- pass B: groups 0..31 (W2 cols 64..223), chunk already prefetched ----
    asm volatile("cp.async.wait_group 0;" ::: "memory");
    __syncthreads();
    // L2-prefetch pass-C gumbel rows before entering pass B
    prefetch_gumbel(gumbel, rowBase, lane, 160, nrows);
    pass_groups(sChunk, sB2, hsw, out, gumbel, rowBase, lane, 0, nrows);

    // ---- pass C: groups 32..63 (W2 cols 224..383), bounded sync restage ----
    __syncthreads();
    for (int i = tid; i < 16000; i += THREADS) {
        int k = i / 160, c = i - k * 160;
        cp_async4(&sChunk[(c / 5) * GSTRIDE + 5 * k + (c % 5)],
                  W2 + k * 384 + 224 + c);
    }
    asm volatile("cp.async.commit_group;");
    asm volatile("cp.async.wait_group 0;" ::: "memory");
    __syncthreads();
    pass_groups(sChunk, sB2, hsw, out, gumbel, rowBase, lane, 32, nrows);
}

extern "C" void kernel_launch(void* const* d_in, const int* in_sizes, int n_in,
                              void* d_out, int out_size)
{
    const float* x      = (const float*)d_in[0];
    const float* W1     = (const float*)d_in[1];
    const float* b1     = (const float*)d_in[2];
    const float* W4     = (const float*)d_in[3];
    const float* b4     = (const float*)d_in[4];
    const float* W2     = (const float*)d_in[5];
    const float* b2     = (const float*)d_in[6];
    const float* gumbel = (const float*)d_in[7];
    float* out = (float*)d_out;

    int nrows = in_sizes[0] / 64;
    int blocks = (nrows + ROWS_PER_BLOCK - 1) / ROWS_PER_BLOCK;

    cudaFuncSetAttribute(mlp_fused_kernel,
                         cudaFuncAttributeMaxDynamicSharedMemorySize, SMEM_BYTES);
    mlp_fused_kernel<<<blocks, THREADS, SMEM_BYTES>>>(
        x, W1, b1, W4, b4, W2, b2, gumbel, out, nrows);
}